// round 11
// baseline (speedup 1.0000x reference)
#include <cuda_runtime.h>
#include <cstdint>

// ---------------------------------------------------------------------------
// Fully fused MSE + SSIM loss, 32x1x512x512 fp32 -> scalar. ONE kernel.
// Round-11: persistent loop + cp.async software pipeline. Next tile's raw
// input is prefetched into smem (LDGSTS, async) while the current tile's
// vconv runs; hconv reads smem (29-cyc LDS, fully covered) instead of
// stalling on 234-577-cyc gmem at every tile start. 40-row tiles keep
// smem at 44KB -> 5 CTAs/SM. Packed fma.rn.f32x2, conflict-free strides,
// fused MSE, one block-reduce + atomic pair per block, last-block epilogue.
// ---------------------------------------------------------------------------

#define H 512
#define W 512
#define B 32
#define OV 502            // valid output size (512 - 11 + 1)
#define TOR 40            // output tile rows
#define TOC 32            // output tile cols
#define TIR 50            // input tile rows (TOR + 10)
#define S2RF 44           // staged input row stride in floats (176B)
#define HBS 33            // hb row stride in ulonglong2 (528B)
#define NTROW 13          // row tiles (13*40 = 520 >= 502)
#define NTILES (16 * NTROW * 32)   // 6656
#define NPERSIST 760               // persistent blocks (~5 per SM)

#define ST_OFF (TIR * S2RF * 4)            // 8800   (targ plane)
#define HB_OFF (2 * TIR * S2RF * 4)        // 17600
#define WS_OFF (HB_OFF + TIR * HBS * 16)   // 44000
#define SMEM_SZ (WS_OFF + 64)              // 44064 -> 5 CTAs/SM

#define NCP (2 * TIR * 11)                 // 1100 cp.async chunks per tile

typedef unsigned long long u64;

__device__ __forceinline__ u64 pk2(float lo, float hi) {
    u64 r; asm("mov.b64 %0, {%1, %2};" : "=l"(r) : "f"(lo), "f"(hi)); return r;
}
__device__ __forceinline__ void upk2(u64 v, float& lo, float& hi) {
    asm("mov.b64 {%0, %1}, %2;" : "=f"(lo), "=f"(hi) : "l"(v));
}
__device__ __forceinline__ u64 ffma2(u64 a, u64 w, u64 c) {
    u64 d; asm("fma.rn.f32x2 %0, %1, %2, %3;" : "=l"(d) : "l"(a), "l"(w), "l"(c));
    return d;
}
__device__ __forceinline__ void cp16(uint32_t dst, const void* src) {
    asm volatile("cp.async.ca.shared.global [%0], [%1], 16;\n"
                 :: "r"(dst), "l"(src));
}

// 11-tap Gaussian, sigma=1.5, normalized; symmetric -> 6 distinct values.
#define GW0 0.00102838f
#define GW1 0.00759875f
#define GW2 0.03600077f
#define GW3 0.10936080f
#define GW4 0.21300549f
#define GW5 0.26601166f
#define DECLARE_W2                                                            \
    const u64 W2[11] = {                                                      \
        pk2(GW0, GW0), pk2(GW1, GW1), pk2(GW2, GW2), pk2(GW3, GW3),           \
        pk2(GW4, GW4), pk2(GW5, GW5),                                         \
        pk2(GW4, GW4), pk2(GW3, GW3), pk2(GW2, GW2), pk2(GW1, GW1),           \
        pk2(GW0, GW0) };

__device__ double g_accum[2] = {0.0, 0.0};   // [0]=mse sum, [1]=ssim sum
__device__ unsigned int g_count = 0;

// Issue the 1100 cp.async chunks for tile (r0, c0) of image base pointers.
// Clamped rows/cols only feed outputs masked in the vconv epilogue.
__device__ __forceinline__ void prefetch_tile(
    int tid, const float* pim, const float* tim,
    int r0, int c0, uint32_t sp_sa, uint32_t st_sa)
{
    #pragma unroll
    for (int k = 0; k < 5; k++) {
        int i = tid + 256 * k;
        if (i < NCP) {
            int fld = (i >= NCP / 2);
            int r = fld ? i - NCP / 2 : i;
            int row = r / 11, chunk = r - row * 11;
            int gr = min(r0 + row, H - 1);
            int gc = min(c0 + 4 * chunk, W - 4);
            const float* src = (fld ? tim : pim) + gr * W + gc;
            uint32_t dst = (fld ? st_sa : sp_sa) + row * (S2RF * 4) + chunk * 16;
            cp16(dst, src);
        }
    }
    asm volatile("cp.async.commit_group;\n");
}

__global__ __launch_bounds__(256, 5) void fused_kernel(
    const float* __restrict__ pred, const float* __restrict__ targ,
    float* __restrict__ out)
{
    extern __shared__ __align__(16) char dsm[];
    float* sp = (float*)dsm;                              // [TIR][S2RF]
    float* st = (float*)(dsm + ST_OFF);
    ulonglong2 (*hb)[HBS] = (ulonglong2(*)[HBS])(dsm + HB_OFF);
    float* ws = (float*)(dsm + WS_OFF);
    const uint32_t sbase = (uint32_t)__cvta_generic_to_shared(dsm);
    const uint32_t sp_sa = sbase, st_sa = sbase + ST_OFF;

    const int tid = threadIdx.x;
    float msum = 0.0f, lsum = 0.0f;

    // tile -> (img, r0, c0)
    #define TILE_COORDS(tile, img, r0, c0)                                    \
        const int img = (tile) / (16 * NTROW);                                \
        const int _rm = (tile) - img * (16 * NTROW);                          \
        const int r0 = (_rm >> 4) * TOR;                                      \
        const int c0 = (_rm & 15) * TOC;

    // ---- prologue: prefetch first tile
    {
        int tile = blockIdx.x;
        if (tile < NTILES) {
            TILE_COORDS(tile, img, r0, c0)
            prefetch_tile(tid, pred + (size_t)img * (H * W),
                          targ + (size_t)img * (H * W), r0, c0, sp_sa, st_sa);
        }
    }

    for (int tile = blockIdx.x; tile < NTILES; tile += NPERSIST) {
        TILE_COORDS(tile, img, r0, c0)

        // s2 staged data ready
        asm volatile("cp.async.wait_group 0;\n" ::: "memory");
        __syncthreads();

        // ---- hconv from staged smem. Row-major tasks (50 rows x 8 cgs):
        // quarter-warp = 8 cgs of one row -> contiguous 128B LDS.128.
        {
            DECLARE_W2
            for (int t = tid; t < TIR * 8; t += 256) {
                int row = t >> 3, cg = t & 7;
                const float* sprow = sp + row * S2RF + 4 * cg;
                const float* strow = st + row * S2RF + 4 * cg;

                float4 P[4], T[4];
                #pragma unroll
                for (int j = 0; j < 4; j++) {
                    P[j] = *(const float4*)(sprow + 4 * j);
                    T[j] = *(const float4*)(strow + 4 * j);
                }

                // MSE: task owns pixels (r0+row, c0+4cg..+3) exactly once.
                if (row < TOR && (r0 + row) < H) {
                    float d0 = P[0].x - T[0].x, d1 = P[0].y - T[0].y;
                    float d2 = P[0].z - T[0].z, d3 = P[0].w - T[0].w;
                    msum = fmaf(d0, d0, msum); msum = fmaf(d1, d1, msum);
                    msum = fmaf(d2, d2, msum); msum = fmaf(d3, d3, msum);
                }

                u64 win[14];
                #pragma unroll
                for (int j = 0; j < 4; j++) {
                    if (4 * j + 0 < 14) win[4 * j + 0] = pk2(P[j].x, T[j].x);
                    if (4 * j + 1 < 14) win[4 * j + 1] = pk2(P[j].y, T[j].y);
                    if (4 * j + 2 < 14) win[4 * j + 2] = pk2(P[j].z, T[j].z);
                    if (4 * j + 3 < 14) win[4 * j + 3] = pk2(P[j].w, T[j].w);
                }

                u64 a0 = 0, a1 = 0, a2 = 0, a3 = 0;
                #pragma unroll
                for (int k = 0; k < 11; k++) {
                    a0 = ffma2(win[k + 0], W2[k], a0);
                    a1 = ffma2(win[k + 1], W2[k], a1);
                    a2 = ffma2(win[k + 2], W2[k], a2);
                    a3 = ffma2(win[k + 3], W2[k], a3);
                }
                #pragma unroll
                for (int k = 0; k < 14; k++) {   // (p,t) -> (p^2+t^2, p*t)
                    float p, tt;
                    upk2(win[k], p, tt);
                    win[k] = pk2(fmaf(p, p, tt * tt), p * tt);
                }
                u64 b0 = 0, b1 = 0, b2 = 0, b3 = 0;
                #pragma unroll
                for (int k = 0; k < 11; k++) {
                    b0 = ffma2(win[k + 0], W2[k], b0);
                    b1 = ffma2(win[k + 1], W2[k], b1);
                    b2 = ffma2(win[k + 2], W2[k], b2);
                    b3 = ffma2(win[k + 3], W2[k], b3);
                }
                // permuted store: storage col = cg + 8j holds actual 4cg+j.
                hb[row][cg +  0] = make_ulonglong2(a0, b0);
                hb[row][cg +  8] = make_ulonglong2(a1, b1);
                hb[row][cg + 16] = make_ulonglong2(a2, b2);
                hb[row][cg + 24] = make_ulonglong2(a3, b3);
            }
        }
        __syncthreads();   // hb ready; s2 fully consumed

        // ---- prefetch NEXT tile into s2 (overlaps vconv below)
        {
            int nxt = tile + NPERSIST;
            if (nxt < NTILES) {
                TILE_COORDS(nxt, nimg, nr0, nc0)
                prefetch_tile(tid, pred + (size_t)nimg * (H * W),
                              targ + (size_t)nimg * (H * W),
                              nr0, nc0, sp_sa, st_sa);
            }
        }

        // ---- vconv streaming: thread owns (storage col, 5 rows).
        {
            DECLARE_W2
            const int c = tid & 31;                    // storage column
            const int acol = 4 * (c & 7) + (c >> 3);   // actual column
            const int rb = (tid >> 5) * 5;             // 0,5,...,35

            u64 accA[5], accB[5];
            #pragma unroll
            for (int j = 0; j < 5; j++) { accA[j] = 0; accB[j] = 0; }

            #pragma unroll
            for (int k = 0; k < 15; k++) {
                ulonglong2 v = hb[rb + k][c];
                #pragma unroll
                for (int j = 0; j < 5; j++) {
                    if (k - j >= 0 && k - j <= 10) {
                        accA[j] = ffma2(v.x, W2[k - j], accA[j]);
                        accB[j] = ffma2(v.y, W2[k - j], accB[j]);
                    }
                }
            }

            const float C1 = 1e-4f, C2 = 9e-4f;
            const int ocol = c0 + acol;
            #pragma unroll
            for (int j = 0; j < 5; j++) {
                int orow = r0 + rb + j;
                if (orow < OV && ocol < OV) {
                    float m1, m2, bsv, bptv;
                    upk2(accA[j], m1, m2);
                    upk2(accB[j], bsv, bptv);
                    float m1s = m1 * m1, m2s = m2 * m2, m12 = m1 * m2;
                    float musum = m1s + m2s;
                    float sigsum = bsv - musum;        // sigma1^2 + sigma2^2
                    float s12 = bptv - m12;            // sigma12
                    float num = (2.0f * m12 + C1) * (2.0f * s12 + C2);
                    float den = (musum + C1) * (sigsum + C2) + 1e-6f;
                    lsum += __fdividef(num, den);
                }
            }
        }
        __syncthreads();   // hb consumed before next tile's hconv overwrites
    }

    // ---- single block reduction of (msum, lsum) after all tiles
    #pragma unroll
    for (int o = 16; o; o >>= 1) {
        msum += __shfl_down_sync(0xffffffffu, msum, o);
        lsum += __shfl_down_sync(0xffffffffu, lsum, o);
    }
    int lane = tid & 31, wid = tid >> 5;
    if (!lane) { ws[wid] = msum; ws[8 + wid] = lsum; }
    __syncthreads();
    if (wid == 0) {
        msum = (lane < 8) ? ws[lane] : 0.0f;
        lsum = (lane < 8) ? ws[8 + lane] : 0.0f;
        #pragma unroll
        for (int o = 4; o; o >>= 1) {
            msum += __shfl_down_sync(0xffffffffu, msum, o);
            lsum += __shfl_down_sync(0xffffffffu, lsum, o);
        }
        if (!lane) {
            atomicAdd(&g_accum[0], (double)msum);
            atomicAdd(&g_accum[1], (double)lsum);
            __threadfence();
            unsigned done = atomicAdd(&g_count, 1u);
            if (done == NPERSIST - 1) {
                // all blocks' fenced atomics visible; read via atomic RMW
                double a0 = atomicAdd(&g_accum[0], 0.0);
                double a1 = atomicAdd(&g_accum[1], 0.0);
                double mse = a0 / (double)(B * H * W);
                double smean = a1 / ((double)B * OV * OV);
                out[0] = (float)(0.6 * mse + 0.4 * (1.0 - smean));
                // reset for next graph replay (replays are serialized)
                g_accum[0] = 0.0;
                g_accum[1] = 0.0;
                g_count = 0u;
            }
        }
    }
}

// ---------------------------------------------------------------------------
extern "C" void kernel_launch(void* const* d_in, const int* in_sizes, int n_in,
                              void* d_out, int out_size)
{
    const float* pred = (const float*)d_in[0];
    const float* targ = (const float*)d_in[1];

    cudaFuncSetAttribute(fused_kernel,
                         cudaFuncAttributeMaxDynamicSharedMemorySize, SMEM_SZ);

    fused_kernel<<<NPERSIST, 256, SMEM_SZ>>>(pred, targ, (float*)d_out);
}

// round 12
// speedup vs baseline: 1.0730x; 1.0730x over previous
#include <cuda_runtime.h>

// ---------------------------------------------------------------------------
// Fully fused MSE + SSIM loss, 32x1x512x512 fp32 -> scalar. ONE kernel.
// Round-12: round-8 compute body + vertical halo REUSE. Each of 704
// persistent blocks walks 8 consecutive row-tiles (flat = strip*11 +
// rowtile); hb is a 64-row ring (slot = global_row & 63). When the next
// tile continues the same strip, its top 10 hconv rows are already in the
// ring -> hconv computes 48 rows instead of 58 (-13.7% hconv FFMA2 and
// LDG). Packed fma.rn.f32x2, conflict-free permuted STS, fused MSE with
// exact run-aware ownership, one reduce+atomic pair per block.
// ---------------------------------------------------------------------------

#define H 512
#define W 512
#define B 32
#define OV 502            // valid output size (512 - 11 + 1)
#define TOR 48            // output tile rows
#define TOC 32            // output tile cols
#define TIR 58            // input tile rows (TOR + 10)
#define HBS 33            // hb row stride in ulonglong2 (528B: coeff 4 mod 32)
#define RING 64           // hb ring rows (power of 2)
#define NTROW 11          // row tiles per strip (11*48 = 528 >= 502)
#define RUN 8             // tiles per persistent block
#define NPERSIST 704      // 704*8 = 5632 = 32*16*11 tiles, single wave

#define HB_BYTES  (RING * HBS * 16)      // 33792
#define SMEM_SZ   (HB_BYTES + 64)        // 33856 -> 5 CTAs/SM (smem)

typedef unsigned long long u64;

__device__ __forceinline__ u64 pk2(float lo, float hi) {
    u64 r; asm("mov.b64 %0, {%1, %2};" : "=l"(r) : "f"(lo), "f"(hi)); return r;
}
__device__ __forceinline__ void upk2(u64 v, float& lo, float& hi) {
    asm("mov.b64 {%0, %1}, %2;" : "=f"(lo), "=f"(hi) : "l"(v));
}
__device__ __forceinline__ u64 ffma2(u64 a, u64 w, u64 c) {
    u64 d; asm("fma.rn.f32x2 %0, %1, %2, %3;" : "=l"(d) : "l"(a), "l"(w), "l"(c));
    return d;
}

// 11-tap Gaussian, sigma=1.5, normalized; symmetric -> 6 distinct values.
#define GW0 0.00102838f
#define GW1 0.00759875f
#define GW2 0.03600077f
#define GW3 0.10936080f
#define GW4 0.21300549f
#define GW5 0.26601166f
#define DECLARE_W2                                                            \
    const u64 W2[11] = {                                                      \
        pk2(GW0, GW0), pk2(GW1, GW1), pk2(GW2, GW2), pk2(GW3, GW3),           \
        pk2(GW4, GW4), pk2(GW5, GW5),                                         \
        pk2(GW4, GW4), pk2(GW3, GW3), pk2(GW2, GW2), pk2(GW1, GW1),           \
        pk2(GW0, GW0) };

__device__ double g_accum[2] = {0.0, 0.0};   // [0]=mse sum, [1]=ssim sum
__device__ unsigned int g_count = 0;

__global__ __launch_bounds__(256, 5) void fused_kernel(
    const float* __restrict__ pred, const float* __restrict__ targ,
    float* __restrict__ out)
{
    extern __shared__ __align__(16) char dsm[];
    ulonglong2 (*hb)[HBS] = (ulonglong2(*)[HBS])dsm;   // 64-row ring
    float* ws = (float*)(dsm + HB_BYTES);

    const int tid = threadIdx.x;
    float msum = 0.0f, lsum = 0.0f;

    const int base = blockIdx.x * RUN;

    #pragma unroll 1
    for (int j = 0; j < RUN; j++) {
        const int flat = base + j;
        const int strip = flat / NTROW;
        const int rowtile = flat - strip * NTROW;
        const int img = strip >> 4;
        const int c0 = (strip & 15) * TOC;
        const int r0 = rowtile * TOR;
        const float* pim = pred + (size_t)img * (H * W);
        const float* tim = targ + (size_t)img * (H * W);

        // reuse top-10 hconv rows iff previous tile (same block) was the
        // previous row-tile of the SAME strip.
        const bool reuse = (j > 0) && (rowtile != 0);
        // next tile (same block) continues this strip -> this tile must
        // MSE-count its bottom 10 rows (the next tile won't process them).
        const bool next_cont = (j < RUN - 1) && (rowtile < NTROW - 1);
        const int rowstart = reuse ? 10 : 0;
        const int ntasks = (TIR - rowstart) * 8;

        // ---- hconv (gmem-direct) into the ring. Row-major tasks:
        // quarter-warp = 8 cgs of one row -> coalesced LDG, conflict-free
        // permuted STS (storage col = cg + 8j).
        {
            DECLARE_W2
            for (int t = tid; t < ntasks; t += 256) {
                int row = rowstart + (t >> 3), cg = t & 7;
                int grow = r0 + row;
                int gr = min(grow, H - 1);
                const float* prow = pim + gr * W;
                const float* trow = tim + gr * W;
                const int cbase = c0 + 4 * cg;

                float4 P[4], T[4];
                #pragma unroll
                for (int jj = 0; jj < 4; jj++) {
                    int gc = min(cbase + 4 * jj, W - 4);  // clamp dups feed
                    P[jj] = *(const float4*)(prow + gc);  // only masked outs
                    T[jj] = *(const float4*)(trow + gc);
                }

                // MSE: exact partition across the run (see header comment).
                if (grow < H && (row < TOR || next_cont)) {
                    float d0 = P[0].x - T[0].x, d1 = P[0].y - T[0].y;
                    float d2 = P[0].z - T[0].z, d3 = P[0].w - T[0].w;
                    msum = fmaf(d0, d0, msum); msum = fmaf(d1, d1, msum);
                    msum = fmaf(d2, d2, msum); msum = fmaf(d3, d3, msum);
                }

                u64 win[14];
                #pragma unroll
                for (int jj = 0; jj < 4; jj++) {
                    if (4 * jj + 0 < 14) win[4 * jj + 0] = pk2(P[jj].x, T[jj].x);
                    if (4 * jj + 1 < 14) win[4 * jj + 1] = pk2(P[jj].y, T[jj].y);
                    if (4 * jj + 2 < 14) win[4 * jj + 2] = pk2(P[jj].z, T[jj].z);
                    if (4 * jj + 3 < 14) win[4 * jj + 3] = pk2(P[jj].w, T[jj].w);
                }

                u64 a0 = 0, a1 = 0, a2 = 0, a3 = 0;
                #pragma unroll
                for (int k = 0; k < 11; k++) {
                    a0 = ffma2(win[k + 0], W2[k], a0);
                    a1 = ffma2(win[k + 1], W2[k], a1);
                    a2 = ffma2(win[k + 2], W2[k], a2);
                    a3 = ffma2(win[k + 3], W2[k], a3);
                }
                #pragma unroll
                for (int k = 0; k < 14; k++) {   // (p,t) -> (p^2+t^2, p*t)
                    float p, tt;
                    upk2(win[k], p, tt);
                    win[k] = pk2(fmaf(p, p, tt * tt), p * tt);
                }
                u64 b0 = 0, b1 = 0, b2 = 0, b3 = 0;
                #pragma unroll
                for (int k = 0; k < 11; k++) {
                    b0 = ffma2(win[k + 0], W2[k], b0);
                    b1 = ffma2(win[k + 1], W2[k], b1);
                    b2 = ffma2(win[k + 2], W2[k], b2);
                    b3 = ffma2(win[k + 3], W2[k], b3);
                }
                // ring store, permuted: storage col cg+8j = actual 4cg+j
                const int slot = grow & (RING - 1);
                hb[slot][cg +  0] = make_ulonglong2(a0, b0);
                hb[slot][cg +  8] = make_ulonglong2(a1, b1);
                hb[slot][cg + 16] = make_ulonglong2(a2, b2);
                hb[slot][cg + 24] = make_ulonglong2(a3, b3);
            }
        }
        __syncthreads();   // ring rows r0..r0+57 all valid

        // ---- vconv streaming from the ring: thread owns (storage col,
        // 6 rows). 16 LDS.128, 24 packed accumulators, SSIM epilogue.
        {
            DECLARE_W2
            const int c = tid & 31;                    // storage column
            const int acol = 4 * (c & 7) + (c >> 3);   // actual column
            const int rb = (tid >> 5) * 6;             // 0,6,...,42

            u64 accA[6], accB[6];
            #pragma unroll
            for (int jj = 0; jj < 6; jj++) { accA[jj] = 0; accB[jj] = 0; }

            #pragma unroll
            for (int k = 0; k < 16; k++) {
                ulonglong2 v = hb[(r0 + rb + k) & (RING - 1)][c];
                #pragma unroll
                for (int jj = 0; jj < 6; jj++) {
                    if (k - jj >= 0 && k - jj <= 10) {
                        accA[jj] = ffma2(v.x, W2[k - jj], accA[jj]);
                        accB[jj] = ffma2(v.y, W2[k - jj], accB[jj]);
                    }
                }
            }

            const float C1 = 1e-4f, C2 = 9e-4f;
            const int ocol = c0 + acol;
            #pragma unroll
            for (int jj = 0; jj < 6; jj++) {
                int orow = r0 + rb + jj;
                if (orow < OV && ocol < OV) {
                    float m1, m2, bsv, bptv;
                    upk2(accA[jj], m1, m2);
                    upk2(accB[jj], bsv, bptv);
                    float m1s = m1 * m1, m2s = m2 * m2, m12 = m1 * m2;
                    float musum = m1s + m2s;
                    float sigsum = bsv - musum;        // sigma1^2 + sigma2^2
                    float s12 = bptv - m12;            // sigma12
                    float num = (2.0f * m12 + C1) * (2.0f * s12 + C2);
                    float den = (musum + C1) * (sigsum + C2) + 1e-6f;
                    lsum += __fdividef(num, den);
                }
            }
        }
        __syncthreads();   // ring consumed before next tile's hconv writes
    }

    // ---- single block reduction of (msum, lsum) after the run
    #pragma unroll
    for (int o = 16; o; o >>= 1) {
        msum += __shfl_down_sync(0xffffffffu, msum, o);
        lsum += __shfl_down_sync(0xffffffffu, lsum, o);
    }
    int lane = tid & 31, wid = tid >> 5;
    if (!lane) { ws[wid] = msum; ws[8 + wid] = lsum; }
    __syncthreads();
    if (wid == 0) {
        msum = (lane < 8) ? ws[lane] : 0.0f;
        lsum = (lane < 8) ? ws[8 + lane] : 0.0f;
        #pragma unroll
        for (int o = 4; o; o >>= 1) {
            msum += __shfl_down_sync(0xffffffffu, msum, o);
            lsum += __shfl_down_sync(0xffffffffu, lsum, o);
        }
        if (!lane) {
            atomicAdd(&g_accum[0], (double)msum);
            atomicAdd(&g_accum[1], (double)lsum);
            __threadfence();
            unsigned done = atomicAdd(&g_count, 1u);
            if (done == NPERSIST - 1) {
                // all blocks' fenced atomics visible; read via atomic RMW
                double a0 = atomicAdd(&g_accum[0], 0.0);
                double a1 = atomicAdd(&g_accum[1], 0.0);
                double mse = a0 / (double)(B * H * W);
                double smean = a1 / ((double)B * OV * OV);
                out[0] = (float)(0.6 * mse + 0.4 * (1.0 - smean));
                // reset for next graph replay (replays are serialized)
                g_accum[0] = 0.0;
                g_accum[1] = 0.0;
                g_count = 0u;
            }
        }
    }
}

// ---------------------------------------------------------------------------
extern "C" void kernel_launch(void* const* d_in, const int* in_sizes, int n_in,
                              void* d_out, int out_size)
{
    const float* pred = (const float*)d_in[0];
    const float* targ = (const float*)d_in[1];

    cudaFuncSetAttribute(fused_kernel,
                         cudaFuncAttributeMaxDynamicSharedMemorySize, SMEM_SZ);

    fused_kernel<<<NPERSIST, 256, SMEM_SZ>>>(pred, targ, (float*)d_out);
}